// round 13
// baseline (speedup 1.0000x reference)
#include <cuda_runtime.h>
#include <math.h>
#include <stdint.h>

#define NBATCH 64
#define LSEQ   2048
#define HDIM   512

typedef unsigned long long u64;

// ---------------------------------------------------------------- helpers
__device__ __forceinline__ void ffma2(u64 &acc, u64 a, u64 b) {
    asm("fma.rn.f32x2 %0, %1, %2, %0;" : "+l"(acc) : "l"(a), "l"(b));
}
__device__ __forceinline__ u64 lds_u64(unsigned addr) {
    u64 v;
    asm volatile("ld.shared.b64 %0, [%1];" : "=l"(v) : "r"(addr));
    return v;
}
__device__ __forceinline__ void lds_v2u64(u64 &a, u64 &b, unsigned addr) {
    asm volatile("ld.shared.v2.b64 {%0,%1}, [%2];" : "=l"(a), "=l"(b) : "r"(addr));
}
__device__ __forceinline__ float hsum2(u64 v) {
    float x, y;
    asm("mov.b64 {%0,%1}, %2;" : "=f"(x), "=f"(y) : "l"(v));
    return x + y;
}
__device__ __forceinline__ unsigned smem_u32(const void* p) {
    unsigned r;
    asm("{ .reg .u64 t; cvta.to.shared.u64 t, %1; cvt.u32.u64 %0, t; }"
        : "=r"(r) : "l"(p));
    return r;
}
__device__ __forceinline__ unsigned mapa_u32(unsigned addr, int rank) {
    unsigned ra;
    asm("mapa.shared::cluster.u32 %0, %1, %2;" : "=r"(ra) : "r"(addr), "r"(rank));
    return ra;
}
__device__ __forceinline__ void st_cluster_v2f32(unsigned raddr, float a, float b) {
    asm volatile("st.shared::cluster.v2.f32 [%0], {%1,%2};"
                 :: "r"(raddr), "f"(a), "f"(b) : "memory");
}
// R12-proven ordering: stores -> fence.acq_rel.cluster -> plain remote arrive;
// consumer's try_wait.parity.acquire.cluster pairs with it.
__device__ __forceinline__ void fence_acqrel_cluster() {
    asm volatile("fence.acq_rel.cluster;" ::: "memory");
}
__device__ __forceinline__ void mbar_arrive_cluster(unsigned raddr) {
    asm volatile("mbarrier.arrive.shared::cluster.b64 _, [%0];"
                 :: "r"(raddr) : "memory");
}
__device__ __forceinline__ void mbar_init(unsigned addr, unsigned cnt) {
    asm volatile("mbarrier.init.shared.b64 [%0], %1;" :: "r"(addr), "r"(cnt) : "memory");
}
__device__ __forceinline__ void mbar_wait_parity(unsigned addr, unsigned parity) {
    asm volatile(
        "{\n\t"
        ".reg .pred P;\n\t"
        "WL_%=:\n\t"
        "mbarrier.try_wait.parity.acquire.cluster.shared::cta.b64 P, [%0], %1, 0x989680;\n\t"
        "@!P bra WL_%=;\n\t"
        "}"
        :: "r"(addr), "r"(parity) : "memory");
}
#define CLUSTER_SYNC() do { \
    asm volatile("barrier.cluster.arrive.aligned;" ::: "memory"); \
    asm volatile("barrier.cluster.wait.aligned;"   ::: "memory"); } while (0)

// ======================================================================
// Kernel 1: Xh = emb[X] @ W_xh^T + b_xh  -> out (in place for the scan)
// (unchanged: measured ~2.0 ms, conflict-free strided tile + f32x2)
// ======================================================================
__global__ __launch_bounds__(256) void xh_gemm_kernel(
    const int* __restrict__ X, const float* __restrict__ emb,
    const float* __restrict__ W_xh, const float* __restrict__ b_xh,
    float* __restrict__ out)
{
    __shared__ __align__(16) float2 As2[8][64];
    __shared__ __align__(16) float2 Bs2[8][64];
    const int tid = threadIdx.x;
    const int m0 = blockIdx.y * 64;
    const int j0 = blockIdx.x * 64;
    const int row = tid >> 2;
    const int kq  = tid & 3;
    const int ty  = tid >> 4;
    const int tx  = tid & 15;

    const int tok = X[m0 + row];
    const float* arow = emb  + (size_t)tok        * HDIM + kq * 4;
    const float* brow = W_xh + (size_t)(j0 + row) * HDIM + kq * 4;

    const unsigned aB = smem_u32(As2);
    const unsigned bB = smem_u32(Bs2);

    u64 acc[4][4];
#pragma unroll
    for (int i = 0; i < 4; i++)
#pragma unroll
        for (int j = 0; j < 4; j++) acc[i][j] = 0ull;

    float4 av = *(const float4*)(arow);
    float4 bv = *(const float4*)(brow);

    for (int k0 = 0; k0 < HDIM; k0 += 16) {
        __syncthreads();
        As2[kq*2+0][row] = make_float2(av.x, av.y);
        As2[kq*2+1][row] = make_float2(av.z, av.w);
        Bs2[kq*2+0][row] = make_float2(bv.x, bv.y);
        Bs2[kq*2+1][row] = make_float2(bv.z, bv.w);
        __syncthreads();
        if (k0 + 16 < HDIM) {
            av = *(const float4*)(arow + k0 + 16);
            bv = *(const float4*)(brow + k0 + 16);
        }
#pragma unroll
        for (int kk2 = 0; kk2 < 8; kk2++) {
            u64 a[4], b[4];
#pragma unroll
            for (int i = 0; i < 4; i++)
                a[i] = lds_u64(aB + (unsigned)(kk2*64 + ty + 16*i) * 8);
#pragma unroll
            for (int i = 0; i < 4; i++)
                b[i] = lds_u64(bB + (unsigned)(kk2*64 + tx + 16*i) * 8);
#pragma unroll
            for (int i = 0; i < 4; i++)
#pragma unroll
                for (int j = 0; j < 4; j++)
                    ffma2(acc[i][j], a[i], b[j]);
        }
    }

    float bx[4];
#pragma unroll
    for (int j = 0; j < 4; j++) bx[j] = b_xh[j0 + tx + 16*j];
#pragma unroll
    for (int i = 0; i < 4; i++) {
        float* orow = out + (size_t)(m0 + ty + 16*i) * HDIM + j0 + tx;
#pragma unroll
        for (int j = 0; j < 4; j++)
            orow[16*j] = hsum2(acc[i][j]) + bx[j];
    }
}

// ======================================================================
// Kernel 2: persistent scan, LOCAL-K + TWO-CHAIN PIPELINE + register W.
// 16 clusters x 8 CTAs; cluster c owns rows [4c,4c+4): chain A = rows
// {4c,4c+1}, chain B = {4c+2,4c+3}. 256 threads; thread owns W rows
// {2tid, 2tid+1} x its CTA's 64-k chunk IN REGISTERS (64 u64).
// Unit(X,i): [prefetch xh; wait X partials(i-1); reduce+tanh -> h(i-1),
// store out] sync [compute z(i)=W*h(i-1); push to j-owners; fence;
// arrive]. Units alternate A,B so each chain's exchange latency is
// hidden under the other chain's work. No W smem traffic at all.
// ======================================================================
#define CL   8
#define ST3  256

// smem float offsets (static smem, ~17.7 KB)
#define OFF_P   0                          // [chain2][phase2][src8][n2][jj64] = 4096
#define OFF_HH  4096                       // [chain2][n2][jj64] = 256
#define OFF_B3  (OFF_HH + 256)             // 64
#define OFF_MB  (OFF_B3 + 64)              // 4 mbarriers (8 floats)
#define SC3_FLOATS (OFF_MB + 8)

__global__ __launch_bounds__(ST3, 1) __cluster_dims__(CL, 1, 1)
void scan_kernel(const float* __restrict__ W_hh,
                 const float* __restrict__ b_hh, float* __restrict__ out)
{
    __shared__ __align__(16) float sm[SC3_FLOATS];
    const unsigned smb = smem_u32(sm);
    const int tid = threadIdx.x;
    int rank;
    asm("mov.u32 %0, %%cluster_ctarank;" : "=r"(rank));
    const int c = blockIdx.x / CL;         // 0..15 cluster = 4 batch rows
    const int w = tid >> 5;                // warp 0..7 -> pushes to rank w

    // ---- W_hh rows {2tid, 2tid+1}, own 64-k chunk, into registers ----
    u64 wreg[2][32];
    {
        const u64* Wg = (const u64*)W_hh;  // 256 u64 per row
        const size_t r0 = (size_t)(2*tid) * 256 + rank * 32;
#pragma unroll
        for (int kp = 0; kp < 32; kp++) {
            wreg[0][kp] = Wg[r0 + kp];
            wreg[1][kp] = Wg[r0 + 256 + kp];
        }
    }
    if (tid < 64) sm[OFF_B3 + tid] = b_hh[rank*64 + tid];
    for (int i2 = tid; i2 < 256; i2 += ST3) sm[OFF_HH + i2] = 0.f;  // h(-1)=0
    if (tid == 0) {
#pragma unroll
        for (int q = 0; q < 4; q++)
            mbar_init(smb + OFF_MB*4 + q*8, ST3);   // 256 arrivals each
    }
    __syncthreads();
    CLUSTER_SYNC();   // peers see mbar init before any remote arrive

    const unsigned rb = mapa_u32(smb, w);          // remote base, dest rank w
    const unsigned pushj = (unsigned)((2*tid) & 63);

    // reduce/output mapping (tid < 128): nn = row-in-chain, jj = j offset
    const int nn = (tid >> 6) & 1, jj = tid & 63;
    const bool red = (tid < 128);
    size_t gb[2];
    gb[0] = (size_t)(c*4 + nn)     * LSEQ * HDIM + rank*64 + jj;
    gb[1] = (size_t)(c*4 + 2 + nn) * LSEQ * HDIM + rank*64 + jj;

    for (int i = 0; i <= LSEQ; i++) {
#pragma unroll
        for (int X = 0; X < 2; X++) {
            // ---- phase 1: finish step i-1 of chain X ----
            float xh = 0.f;
            if (i >= 1 && red) xh = out[gb[X] + (size_t)(i-1) * HDIM];
            if (i >= 1) {
                mbar_wait_parity(smb + OFF_MB*4 + (X*2 + ((i-1)&1))*8,
                                 (unsigned)(((i-1) >> 1) & 1));
                if (red) {
                    const float* pb = sm + OFF_P + (X*2 + ((i-1)&1))*1024
                                    + nn*64 + jj;
                    float s = 0.f;
#pragma unroll
                    for (int src = 0; src < 8; src++) s += pb[src*128];
                    float v = tanhf(s + sm[OFF_B3 + jj] + xh);
                    sm[OFF_HH + X*128 + nn*64 + jj] = v;
                    out[gb[X] + (size_t)(i-1) * HDIM] = v;
                }
            }
            __syncthreads();   // h(i-1) complete before compute reads it

            // ---- phase 2: compute step i of chain X, push partials ----
            if (i < LSEQ) {
                u64 a00 = 0, a01 = 0, a10 = 0, a11 = 0;  // [jl][n]
                const unsigned hb = smb + (OFF_HH + X*128) * 4;
#pragma unroll
                for (int kp = 0; kp < 32; kp += 2) {
                    u64 h0a, h0b, h1a, h1b;
                    lds_v2u64(h0a, h0b, hb + kp*8);          // n=0, broadcast
                    lds_v2u64(h1a, h1b, hb + 256 + kp*8);    // n=1
                    ffma2(a00, wreg[0][kp], h0a); ffma2(a00, wreg[0][kp+1], h0b);
                    ffma2(a01, wreg[0][kp], h1a); ffma2(a01, wreg[0][kp+1], h1b);
                    ffma2(a10, wreg[1][kp], h0a); ffma2(a10, wreg[1][kp+1], h0b);
                    ffma2(a11, wreg[1][kp], h1a); ffma2(a11, wreg[1][kp+1], h1b);
                }
                const unsigned pB = (unsigned)((OFF_P + (X*2 + (i&1))*1024
                                               + rank*128) * 4);
                st_cluster_v2f32(rb + pB + pushj*4,
                                 hsum2(a00), hsum2(a10));          // n=0: j,j+1
                st_cluster_v2f32(rb + pB + 256 + pushj*4,
                                 hsum2(a01), hsum2(a11));          // n=1
                fence_acqrel_cluster();
                mbar_arrive_cluster(rb + (unsigned)(OFF_MB*4)
                                    + (unsigned)((X*2 + (i&1))*8));
            }
        }
    }

    CLUSTER_SYNC();   // keep smem alive until all peers drained
}

// ======================================================================
extern "C" void kernel_launch(void* const* d_in, const int* in_sizes, int n_in,
                              void* d_out, int out_size) {
    const int*   X    = (const int*)d_in[0];
    const float* emb  = (const float*)d_in[1];
    const float* W_hh = (const float*)d_in[2];
    const float* b_hh = (const float*)d_in[3];
    const float* W_xh = (const float*)d_in[4];
    const float* b_xh = (const float*)d_in[5];
    float* out = (float*)d_out;
    (void)in_sizes; (void)n_in; (void)out_size;

    dim3 g1(HDIM / 64, (NBATCH * LSEQ) / 64);   // (8, 2048)
    xh_gemm_kernel<<<g1, 256>>>(X, emb, W_xh, b_xh, out);

    scan_kernel<<<16 * CL, ST3>>>(W_hh, b_hh, out);
}